// round 12
// baseline (speedup 1.0000x reference)
#include <cuda_runtime.h>
#include <cstdint>

#define LROW     32768
#define NTHREADS 64
#define CHUNK    8
#define TILE     512                  // NTHREADS * CHUNK
#define NTILES   64                   // LROW / TILE
#define CTAS     (148 * 12)           // persistent
#define XF4      140                  // x stage: 132 float4 used + swz pad
#define AF4      264                  // act stage: 259 float4 used + swz pad

// Kaiser-sinc taps for kaiser_sinc_filter1d(0.25, 0.3, 12) (see round 10).
#define T0 ( 0.00202895f)
#define T1 ( 0.00938947f)
#define T2 (-0.02554328f)
#define T3 (-0.05765736f)
#define T4 ( 0.12857258f)
#define T5 ( 0.44320973f)

// XOR swizzle at float4 granularity.
__device__ __forceinline__ int swz(int v) { return v ^ ((v >> 3) & 7); }

__device__ __forceinline__ float4 ldg_f4_clamped(const float* __restrict__ xr, int j0) {
    float t[4];
#pragma unroll
    for (int u = 0; u < 4; ++u) {
        int gi = j0 + u;
        gi = max(0, min(gi, LROW - 1));
        t[u] = __ldg(xr + gi);
    }
    return make_float4(t[0], t[1], t[2], t[3]);
}

// Fused up-2x (12-tap polyphase) -> LeakyReLU(0.1) -> down-2x.
// TWO-STAGE SHARED-ACT form: stage A computes each act slot pair (E,O)
// exactly ONCE (8 per thread + 5 tile-halo) into swizzled smem; stage B
// reads 13 pairs and applies the down filter. Removes the 1.625x up-stage
// slot redundancy of the register-blocked form without register growth.
// All taps immediates (FFMA-imm rt=1). Persistent 64-thread CTAs.
__global__ __launch_bounds__(NTHREADS, 12)
void aa_act_kernel(const float* __restrict__ x,
                   const float* __restrict__ upf,
                   const float* __restrict__ dnf,
                   float* __restrict__ out,
                   int total_tiles)
{
    __shared__ __align__(16) float4 sx[2][XF4];   // x window, double-buffered
    __shared__ __align__(16) float4 sact[AF4];    // (E,O) pairs, per-tile

    const float FE[6] = {2*T0, 2*T2, 2*T4, 2*T5, 2*T3, 2*T1};
    const float FO[6] = {2*T1, 2*T3, 2*T5, 2*T4, 2*T2, 2*T0};
    const float DN[12] = {T0,T1,T2,T3,T4,T5,T5,T4,T3,T2,T1,T0};

    const int tid = threadIdx.x;
    // x reads: float4 idx 2t..2t+3 -> xv[i]=x[o-8+i], i=0..15
    int rx[4];
#pragma unroll
    for (int k = 0; k < 4; ++k) rx[k] = swz(2 * tid + k);
    // act read/write: float4 idx 4t+j (writes j=0..3, reads j=0..6)
    int ia[7];
#pragma unroll
    for (int j = 0; j < 7; ++j) ia[j] = swz(4 * tid + j);
    const int wx0 = swz(tid), wx1 = swz(tid + 64), wx2 = swz(tid + 128);

    int tile = blockIdx.x;
    if (tile >= total_tiles) return;

    // Stage tile t_'s x window [o0-8 .. o0+TILE+7] (row-clamped at edges).
    auto ldg_stage = [&](int t_, float4& a, float4& b, float4& c) {
        const int tpos = t_ & (NTILES - 1);
        const int o0   = tpos * TILE;
        const float* xr = x + (size_t)(t_ >> 6) * LROW;
        if ((tpos != 0) & (tpos != NTILES - 1)) {
            const float4* p = (const float4*)(xr + (o0 - 8));   // 16B aligned
            a = __ldg(p + tid);
            b = __ldg(p + tid + 64);
            if (tid < 4) c = __ldg(p + tid + 128);
        } else {
            a = ldg_f4_clamped(xr, o0 - 8 + 4 * tid);
            b = ldg_f4_clamped(xr, o0 - 8 + 4 * (tid + 64));
            if (tid < 4) c = ldg_f4_clamped(xr, o0 - 8 + 4 * (tid + 128));
        }
    };
    auto sts_stage = [&](int b_, const float4& a, const float4& bb, const float4& c) {
        sx[b_][wx0] = a;
        sx[b_][wx1] = bb;
        if (tid < 4) sx[b_][wx2] = c;
    };
    // Scalar float read from swizzled x buffer (halo slots only).
    auto lds_f = [&](int b_, int j) -> float {
        const float* p = (const float*)&sx[b_][swz(j >> 2)];
        return p[j & 3];
    };

    {   // prologue
        float4 a, b, c;
        ldg_stage(tile, a, b, c);
        sts_stage(0, a, b, c);
    }
    __syncthreads();

    int buf = 0;
    for (; tile < total_tiles; tile += CTAS) {
        const int ntile = tile + CTAS;
        const bool have_next = ntile < total_tiles;
        float4 na, nb, nc;
        if (have_next) ldg_stage(ntile, na, nb, nc);

        const int row = tile >> 6;
        const int o   = (tile & (NTILES - 1)) * TILE + tid * CHUNK;

        // ---- Stage A: up-sample + lrelu, 8 owned slots per thread ----
        // xv[i] = x[o-8+i]; slot t (global s=o+t) reads xv[t+3 .. t+8].
        float xv[16];
#pragma unroll
        for (int k = 0; k < 4; ++k) {
            float4 q = sx[buf][rx[k]];
            xv[4 * k + 0] = q.x; xv[4 * k + 1] = q.y;
            xv[4 * k + 2] = q.z; xv[4 * k + 3] = q.w;
        }
#pragma unroll
        for (int t2 = 0; t2 < 4; ++t2) {           // 2 slots per iteration
            float4 pk;
#pragma unroll
            for (int h = 0; h < 2; ++h) {
                const int t = 2 * t2 + h;
                float se = FE[0] * xv[t + 3];
                float so = FO[0] * xv[t + 3];
#pragma unroll
                for (int e = 1; e < 6; ++e) {
                    se = fmaf(FE[e], xv[t + 3 + e], se);
                    so = fmaf(FO[e], xv[t + 3 + e], so);
                }
                float Et = fmaf(0.45f, fabsf(se), 0.55f * se);
                float Ot = fmaf(0.45f, fabsf(so), 0.55f * so);
                if (h == 0) { pk.x = Et; pk.y = Ot; }
                else        { pk.z = Et; pk.w = Ot; }
            }
            sact[ia[t2]] = pk;                     // pairs 8t+2k, 8t+2k+1
        }
        // Tile-halo slots rel 512..516 (5 threads): window x[s-5..s] ->
        // staged j = s+3 .. s+8 = 515+tid .. 520+tid.
        if (tid < 5) {
            float w[6];
#pragma unroll
            for (int e = 0; e < 6; ++e) w[e] = lds_f(buf, 515 + tid + e);
            float se = FE[0] * w[0], so = FO[0] * w[0];
#pragma unroll
            for (int e = 1; e < 6; ++e) {
                se = fmaf(FE[e], w[e], se);
                so = fmaf(FO[e], w[e], so);
            }
            float Et = fmaf(0.45f, fabsf(se), 0.55f * se);
            float Ot = fmaf(0.45f, fabsf(so), 0.55f * so);
            const int pidx = 512 + tid;
            float2* pp = (float2*)((char*)&sact[swz(pidx >> 1)] + (pidx & 1) * 8);
            *pp = make_float2(Et, Ot);
        }
        __syncthreads();                            // acts ready; x reads done

        // Park next tile's x window (safe after the barrier).
        if (have_next) sts_stage(buf ^ 1, na, nb, nc);

        // ---- Stage B: down-sample from shared act pairs ----
        float PE[14], PO[14];
#pragma unroll
        for (int j = 0; j < 7; ++j) {
            float4 v = sact[ia[j]];
            PE[2 * j]     = v.x; PO[2 * j]     = v.y;
            PE[2 * j + 1] = v.z; PO[2 * j + 1] = v.w;
        }
        // Row-edge act-index fixups (act clamps to act[0] / act[2L-1]).
        if (o == 0) {
            float a0 = PE[2];                       // act[0]
            PE[0] = a0; PE[1] = a0;
            PO[0] = a0; PO[1] = a0; PO[2] = a0;
        }
        if (o == LROW - CHUNK) {
            float aL = PO[10];                      // act[2L-1]
            PE[10] = aL; PE[11] = aL; PE[12] = aL;
            PO[11] = aL; PO[12] = aL;
        }

        float acc[CHUNK];
#pragma unroll
        for (int q = 0; q < CHUNK; ++q) {
            float a = DN[0] * PO[q];
            a = fmaf(DN[1], PE[q], a);
#pragma unroll
            for (int m = 1; m < 6; ++m) {
                a = fmaf(DN[2 * m],     PO[q + m], a);
                a = fmaf(DN[2 * m + 1], PE[q + m], a);
            }
            acc[q] = a;
        }

        float4* op = (float4*)(out + (size_t)row * LROW + o);
        op[0] = make_float4(acc[0], acc[1], acc[2], acc[3]);
        op[1] = make_float4(acc[4], acc[5], acc[6], acc[7]);

        __syncthreads();                            // act reads done before reuse
        buf ^= 1;
    }
}

extern "C" void kernel_launch(void* const* d_in, const int* in_sizes, int n_in,
                              void* d_out, int out_size)
{
    const float* x   = (const float*)d_in[0];
    const float* upf = (const float*)d_in[1];
    const float* dnf = (const float*)d_in[2];
    float* out = (float*)d_out;

    const int rows = in_sizes[0] / LROW;           // 8*128 = 1024
    const int total_tiles = rows * NTILES;         // 65536
    aa_act_kernel<<<CTAS, NTHREADS>>>(x, upf, dnf, out, total_tiles);
}